// round 3
// baseline (speedup 1.0000x reference)
#include <cuda_runtime.h>
#include <cstdint>
#include <cstdio>

// Problem constants
#define Bq   64
#define Sq   2048
#define INq  208
#define Hq   100
#define Gq   300      // 3*H gate rows
#define OUTq 98
#define Mq   (Bq * Sq)   // 131072 rows

// ---------------------------------------------------------------------------
// Scratch (static __device__ arrays — allocation is forbidden)
// ---------------------------------------------------------------------------
__device__ float g_xg[(size_t)Mq * Gq];  // 157 MB: xg0, then reused for xg1
__device__ float g_y [(size_t)Mq * Hq];  //  52 MB: y0, then reused for y1

// ---------------------------------------------------------------------------
// GEMM with bias: C[m][n] = bias[n] + sum_k A[m][k] * W[n][k]
// A: M x K row-major, W: N x K row-major (so this is A @ W^T), C: M x N.
// M is always a multiple of 128 here; K always a multiple of 4; N guarded.
// BM=BN=128, BK=4, 256 threads, 8x8 per-thread microtile.
// ---------------------------------------------------------------------------
#define BM 128
#define BN 128
#define BK 4

__global__ __launch_bounds__(256) void gemm_bias(
    const float* __restrict__ A, const float* __restrict__ W,
    const float* __restrict__ bias, float* __restrict__ C,
    int N, int K)
{
    __shared__ float As[BK][BM + 4];
    __shared__ float Ws[BK][BN + 4];

    const int n0  = blockIdx.x * BN;
    const int m0  = blockIdx.y * BM;
    const int tid = threadIdx.x;
    const int tx  = tid & 15;
    const int ty  = tid >> 4;

    float c[8][8];
#pragma unroll
    for (int i = 0; i < 8; i++)
#pragma unroll
        for (int j = 0; j < 8; j++) c[i][j] = 0.f;

    // Loader role: threads 0..127 stream A rows, threads 128..255 stream W rows.
    const int  lrow = tid & 127;
    const bool isA  = tid < 128;
    const float* src;
    bool valid;
    if (isA) { src = A + (size_t)(m0 + lrow) * K; valid = true; }
    else     { src = W + (size_t)(n0 + lrow) * K; valid = (n0 + lrow) < N; }
    float (*dst)[BM + 4] = isA ? As : Ws;

    for (int k0 = 0; k0 < K; k0 += BK) {
        float4 v = valid ? *(const float4*)(src + k0)
                         : make_float4(0.f, 0.f, 0.f, 0.f);
        __syncthreads();   // protect previous tile's readers
        dst[0][lrow] = v.x; dst[1][lrow] = v.y;
        dst[2][lrow] = v.z; dst[3][lrow] = v.w;
        __syncthreads();
#pragma unroll
        for (int k = 0; k < BK; k++) {
            float af[8], bf[8];
#pragma unroll
            for (int i = 0; i < 8; i++) af[i] = As[k][ty * 8 + i];
#pragma unroll
            for (int j = 0; j < 8; j++) bf[j] = Ws[k][tx * 8 + j];
#pragma unroll
            for (int i = 0; i < 8; i++)
#pragma unroll
                for (int j = 0; j < 8; j++) c[i][j] += af[i] * bf[j];
        }
    }

#pragma unroll
    for (int i = 0; i < 8; i++) {
        const size_t m = (size_t)m0 + ty * 8 + i;
#pragma unroll
        for (int j = 0; j < 8; j++) {
            const int n = n0 + tx * 8 + j;
            if (n < N) C[m * N + n] = c[i][j] + bias[n];
        }
    }
}

// ---------------------------------------------------------------------------
// GRU recurrence for one layer. One CTA per batch element (64 CTAs, fully
// independent). 640 threads; threads t<600 form (gate g = t>>1, K-half = t&1)
// pairs. Each thread keeps its 50 w_hh weights packed as 25 f32x2 pairs in
// registers; the h vector is broadcast from SMEM; packed fma.rn.f32x2 does
// 2 fp32 FMAs per issued instruction (sm_103a). K-halves combine via shfl.
// xg[b,t,:] is prefetched one step ahead into registers.
// ---------------------------------------------------------------------------
__global__ __launch_bounds__(640, 1) void gru_rec(
    const float* __restrict__ xg,     // [B][S][300] precomputed input gates (+b_ih)
    const float* __restrict__ w_hh,   // [300][100]
    const float* __restrict__ b_hh,   // [300]
    const float* __restrict__ h0,     // [B][100] (this layer's slice)
    float* __restrict__ y)            // [B][S][100] output
{
    __shared__ float h_s[2][112];     // double-buffered hidden state
    __shared__ float hg_s[Gq];
    __shared__ float xg_s[Gq];

    const int b   = blockIdx.x;
    const int tid = threadIdx.x;

    unsigned long long wp[25];
    float bhh = 0.f;
    if (tid < 600) {
        const int g = tid >> 1, half = tid & 1;
        const float* wrow = w_hh + g * Hq + half * 50;
#pragma unroll
        for (int j = 0; j < 25; j++) {
            const float a  = __ldg(wrow + 2 * j);
            const float bb = __ldg(wrow + 2 * j + 1);
            asm("mov.b64 %0, {%1, %2};" : "=l"(wp[j]) : "f"(a), "f"(bb));
        }
        if (half == 0) bhh = b_hh[g];
    }
    if (tid < Hq) h_s[0][tid] = h0[b * Hq + tid];

    const float* xg_b = xg + (size_t)b * Sq * Gq;
    float*       y_b  = y  + (size_t)b * Sq * Hq;

    float xg_pref = (tid < Gq) ? xg_b[tid] : 0.f;
    __syncthreads();

    int cur = 0;
    for (int t = 0; t < Sq; t++) {
        // stash this step's xg (loaded last iteration) into SMEM
        if (tid < Gq) xg_s[tid] = xg_pref;

        // matvec: hg[g] = w_hh[g,:] . h  (split K in halves of 50)
        float acc = 0.f;
        if (tid < 600) {
            const int half = tid & 1;
            const unsigned long long* hp =
                (const unsigned long long*)(&h_s[cur][half * 50]);
            unsigned long long a0 = 0ull, a1 = 0ull;
#pragma unroll
            for (int j = 0; j < 25; j++) {
                if (j & 1) {
                    asm("fma.rn.f32x2 %0, %1, %2, %0;"
                        : "+l"(a1) : "l"(wp[j]), "l"(hp[j]));
                } else {
                    asm("fma.rn.f32x2 %0, %1, %2, %0;"
                        : "+l"(a0) : "l"(wp[j]), "l"(hp[j]));
                }
            }
            unsigned long long asum;
            asm("add.rn.f32x2 %0, %1, %2;" : "=l"(asum) : "l"(a0), "l"(a1));
            float lo, hi;
            asm("mov.b64 {%0, %1}, %2;" : "=f"(lo), "=f"(hi) : "l"(asum));
            acc = lo + hi;
        }
        // combine the two K-halves (pairs 2g, 2g+1 are always warp-adjacent)
        acc += __shfl_down_sync(0xffffffffu, acc, 1);
        if (tid < 600 && (tid & 1) == 0) hg_s[tid >> 1] = acc + bhh;

        // prefetch next step's xg while the rest of this step proceeds
        if (tid < Gq && t + 1 < Sq) xg_pref = xg_b[(size_t)(t + 1) * Gq + tid];

        __syncthreads();

        // gate math: threads j < 100
        if (tid < Hq) {
            const float xr = xg_s[tid], xz = xg_s[Hq + tid], xn = xg_s[2 * Hq + tid];
            const float hr = hg_s[tid], hz = hg_s[Hq + tid], hn = hg_s[2 * Hq + tid];
            const float r  = __fdividef(1.f, 1.f + __expf(-(xr + hr)));
            const float z  = __fdividef(1.f, 1.f + __expf(-(xz + hz)));
            const float na = xn + r * hn;
            const float e  = __expf(-2.f * fabsf(na));
            const float nt = copysignf(__fdividef(1.f - e, 1.f + e), na);
            const float hnew = (1.f - z) * nt + z * h_s[cur][tid];
            h_s[cur ^ 1][tid] = hnew;
            y_b[(size_t)t * Hq + tid] = hnew;
        }
        cur ^= 1;
        __syncthreads();
    }
}

// ---------------------------------------------------------------------------
// Launch: 5 kernels on the default stream (graph-capturable, no allocs).
//   1. xg0 = seq @ w_ih_l0^T + b_ih_l0           (GEMM, K=208)
//   2. layer-0 scan -> y0                        (recurrence)
//   3. xg1 = y0 @ w_ih_l1^T + b_ih_l1            (GEMM, K=100, reuses g_xg)
//   4. layer-1 scan -> y1                        (recurrence, reuses g_y)
//   5. out = y1 @ w_out^T + b_out                (GEMM, N=98)
// ---------------------------------------------------------------------------
extern "C" void kernel_launch(void* const* d_in, const int* in_sizes, int n_in,
                              void* d_out, int out_size)
{
    (void)in_sizes; (void)n_in; (void)out_size;
    const float* seq     = (const float*)d_in[0];
    const float* h0      = (const float*)d_in[1];   // [2][B][H]
    const float* w_ih_l0 = (const float*)d_in[2];
    const float* w_hh_l0 = (const float*)d_in[3];
    const float* b_ih_l0 = (const float*)d_in[4];
    const float* b_hh_l0 = (const float*)d_in[5];
    const float* w_ih_l1 = (const float*)d_in[6];
    const float* w_hh_l1 = (const float*)d_in[7];
    const float* b_ih_l1 = (const float*)d_in[8];
    const float* b_hh_l1 = (const float*)d_in[9];
    const float* w_out   = (const float*)d_in[10];
    const float* b_out   = (const float*)d_in[11];
    float* out = (float*)d_out;

    float* xg = nullptr;
    float* y  = nullptr;
    cudaGetSymbolAddress((void**)&xg, g_xg);
    cudaGetSymbolAddress((void**)&y,  g_y);

    dim3 g300((Gq + BN - 1) / BN, Mq / BM);   // (3, 1024)
    dim3 gout((OUTq + BN - 1) / BN, Mq / BM); // (1, 1024)

    gemm_bias<<<g300, 256>>>(seq, w_ih_l0, b_ih_l0, xg, Gq, INq);
    gru_rec  <<<Bq, 640>>>(xg, w_hh_l0, b_hh_l0, h0,            y);
    gemm_bias<<<g300, 256>>>(y, w_ih_l1, b_ih_l1, xg, Gq, Hq);
    gru_rec  <<<Bq, 640>>>(xg, w_hh_l1, b_hh_l1, h0 + Bq * Hq,  y);
    gemm_bias<<<gout, 256>>>(y, w_out, b_out, out, OUTq, Hq);
}